// round 4
// baseline (speedup 1.0000x reference)
#include <cuda_runtime.h>

// FastFood layer: out[n, :] = 1/32 * [cos(t), sin(t)] + bias,
//   t = (1/32) * S .* FWHT( G .* Perm( FWHT( B .* x ) ) )   per stack.
// D = 1024, STACK = 4, out row = 8192 floats.
//
// One block = one (row, stack). 256 threads, radix-4 FWHT in shared memory
// (5 passes for 10 stages). First pass fused with the global x*B load,
// last pass fused with the scale/sincos/store epilogue. The permutation
// gather between the two FWHTs feeds FWHT2's first pass directly in
// registers. Shared buffer padded +1 float per 16 to cap bank conflicts.

#define DD 1024
#define SSTACK 4

__device__ __forceinline__ int padi(int e) { return e + (e >> 4); }

// One radix-4 pass: applies butterfly stages (st, 2*st) in place.
// Thread k owns the disjoint group {i, i+st, i+2st, i+3st}.
__device__ __forceinline__ void bpass(float* hs, int k, int s2) {
    const int st = 1 << s2;
    const int i  = ((k >> s2) << (s2 + 2)) | (k & (st - 1));
    float a = hs[padi(i)];
    float b = hs[padi(i + st)];
    float c = hs[padi(i + 2 * st)];
    float d = hs[padi(i + 3 * st)];
    float u0 = a + b, u1 = a - b, u2 = c + d, u3 = c - d;
    hs[padi(i)]          = u0 + u2;
    hs[padi(i + st)]     = u1 + u3;
    hs[padi(i + 2 * st)] = u0 - u2;
    hs[padi(i + 3 * st)] = u1 - u3;
}

__global__ __launch_bounds__(256)
void fastfood_kernel(const float* __restrict__ x,
                     const float* __restrict__ B,
                     const float* __restrict__ G,
                     const float* __restrict__ S,
                     const float* __restrict__ bias,
                     const int*   __restrict__ P,
                     float* __restrict__ out)
{
    __shared__ float hs[DD + DD / 16];   // 1088 floats, +1 pad per 16
    const int k   = threadIdx.x;         // 0..255
    const int row = blockIdx.x >> 2;
    const int s   = blockIdx.x & 3;
    const int sb  = s * DD;

    // ---- FWHT #1, stages (1,2) fused with x*B load (float4, coalesced) ----
    {
        float4 xv = ((const float4*)(x + (size_t)row * DD))[k];
        float4 bv = ((const float4*)(B + sb))[k];
        float a = xv.x * bv.x, b = xv.y * bv.y;
        float c = xv.z * bv.z, d = xv.w * bv.w;
        float u0 = a + b, u1 = a - b, u2 = c + d, u3 = c - d;
        const int i = 4 * k;
        hs[padi(i)]     = u0 + u2;
        hs[padi(i + 1)] = u1 + u3;
        hs[padi(i + 2)] = u0 - u2;
        hs[padi(i + 3)] = u1 - u3;
    }
    __syncthreads();
    bpass(hs, k, 2); __syncthreads();   // stages 4,8
    bpass(hs, k, 4); __syncthreads();   // stages 16,32
    bpass(hs, k, 6); __syncthreads();   // stages 64,128
    bpass(hs, k, 8); __syncthreads();   // stages 256,512

    // ---- permutation gather (within-stack) * G, straight into registers ----
    int4   pv = ((const int4*)(P + sb))[k];
    float4 gv = ((const float4*)(G + sb))[k];
    float g0 = hs[padi(pv.x - sb)] * gv.x;
    float g1 = hs[padi(pv.y - sb)] * gv.y;
    float g2 = hs[padi(pv.z - sb)] * gv.z;
    float g3 = hs[padi(pv.w - sb)] * gv.w;
    __syncthreads();   // all gathers done before hs is overwritten

    // ---- FWHT #2, stages (1,2) on gathered registers ----
    {
        float u0 = g0 + g1, u1 = g0 - g1, u2 = g2 + g3, u3 = g2 - g3;
        const int i = 4 * k;
        hs[padi(i)]     = u0 + u2;
        hs[padi(i + 1)] = u1 + u3;
        hs[padi(i + 2)] = u0 - u2;
        hs[padi(i + 3)] = u1 - u3;
    }
    __syncthreads();
    bpass(hs, k, 2); __syncthreads();
    bpass(hs, k, 4); __syncthreads();
    bpass(hs, k, 6); __syncthreads();

    // ---- final stages (256,512) in registers + fused epilogue ----
    {
        float a = hs[padi(k)];
        float b = hs[padi(k + 256)];
        float c = hs[padi(k + 512)];
        float d = hs[padi(k + 768)];
        float u0 = a + b, u1 = a - b, u2 = c + d, u3 = c - d;
        float v0 = u0 + u2, v1 = u1 + u3, v2 = u0 - u2, v3 = u1 - u3;
        float v[4] = {v0, v1, v2, v3};   // element e = k + 256*m holds v[m]

        const float invsd = 0.03125f;    // 1/(sigma*sqrt(1024))
        const float rsq   = 0.03125f;    // sqrt(1/1024)
        float* orow = out + (size_t)row * (2 * SSTACK * DD) + sb;
        const float* Srow = S + sb;
        const float* bc   = bias + sb;
        const float* bsn  = bias + SSTACK * DD + sb;
        #pragma unroll
        for (int m = 0; m < 4; m++) {
            const int e = k + 256 * m;   // coalesced per m
            float t = invsd * v[m] * Srow[e];
            float sn, cs;
            sincosf(t, &sn, &cs);
            orow[e]               = rsq * cs + bc[e];
            orow[SSTACK * DD + e] = rsq * sn + bsn[e];
        }
    }
}

extern "C" void kernel_launch(void* const* d_in, const int* in_sizes, int n_in,
                              void* d_out, int out_size) {
    // metadata order: x, B, G, S, bias, H (unused: FWHT replaces it), P
    const float* x    = (const float*)d_in[0];
    const float* B    = (const float*)d_in[1];
    const float* G    = (const float*)d_in[2];
    const float* S    = (const float*)d_in[3];
    const float* bias = (const float*)d_in[4];
    const int*   P    = (const int*)d_in[6];
    float* out = (float*)d_out;

    const int nrows = in_sizes[0] / DD;          // 8192
    dim3 grid(nrows * SSTACK);                   // one block per (row, stack)
    fastfood_kernel<<<grid, 256>>>(x, B, G, S, bias, P, out);
}

// round 5
// speedup vs baseline: 1.2759x; 1.2759x over previous
#include <cuda_runtime.h>

// FastFood layer: out[n, :] = 1/32 * [cos(t), sin(t)] + bias,
//   t = (1/32) * S .* FWHT( G .* Perm( FWHT( B .* x ) ) )   per stack.
// D = 1024, STACK = 4, out row = 8192 floats.
//
// One block = one (row, stack), 256 threads, 4 elements/thread.
// FWHT_1024 factored as: 2 bits in registers (radix-4), 5 bits across lanes
// (__shfl_xor), 3 bits cross-warp via ONE smem exchange (2 bits radix-4 in
// registers + 1 bit via shfl mask 16). Stages commute, so order is free.
// Only smem traffic: one exchange per FWHT + the permutation gather.
// XOR bank swizzle makes both the natural-order (e=4k+r) and strided
// (e=j*256+l4*128+w*16+lo) access patterns conflict-free.

#define DD 1024
#define SSTACK 4

// bank swizzle: permutes addresses within each 32-float block
__device__ __forceinline__ int sw(int e) {
    int b = (e & 31) ^ ((e >> 5) & 3) ^ (((e >> 7) & 1) << 4) ^ (((e >> 8) & 3) << 2);
    return (e & ~31) | b;
}

// radix-4 butterfly over v[0..3] holding {e, e+st, e+2st, e+3st}
__device__ __forceinline__ void r4(float v[4]) {
    float u0 = v[0] + v[1], u1 = v[0] - v[1];
    float u2 = v[2] + v[3], u3 = v[2] - v[3];
    v[0] = u0 + u2; v[1] = u1 + u3;
    v[2] = u0 - u2; v[3] = u1 - u3;
}

// one butterfly stage across lanes differing in bit mask m
__device__ __forceinline__ void shstage(float v[4], int l, int m) {
    #pragma unroll
    for (int r = 0; r < 4; r++) {
        float o = __shfl_xor_sync(0xffffffffu, v[r], m);
        v[r] = (l & m) ? (o - v[r]) : (v[r] + o);
    }
}

// 7 low stages: b0,b1 in registers; b2..b6 across lanes
__device__ __forceinline__ void fwht_low7(float v[4], int l) {
    r4(v);
    shstage(v, l, 1);
    shstage(v, l, 2);
    shstage(v, l, 4);
    shstage(v, l, 8);
    shstage(v, l, 16);
}

__global__ __launch_bounds__(256)
void fastfood_kernel(const float* __restrict__ x,
                     const float* __restrict__ B,
                     const float* __restrict__ G,
                     const float* __restrict__ S,
                     const float* __restrict__ bias,
                     const int*   __restrict__ P,
                     float* __restrict__ out)
{
    __shared__ float hs[DD];
    const int k  = threadIdx.x;      // 0..255
    const int w  = k >> 5;           // warp 0..7
    const int l  = k & 31;           // lane
    const int l4 = (l >> 4) & 1;
    const int lo = l & 15;
    const int row = blockIdx.x >> 2;
    const int s   = blockIdx.x & 3;
    const int sb  = s << 10;

    // phase-1 layout: reg r holds element e1 = 4k + r  (bits: r=b1b0, l=b6..b2, w=b9..b7)
    // phase-2 layout: reg j holds element e2 = j*256 + l4*128 + w*16 + lo
    const int e1b = k << 2;
    const int e2b = (l4 << 7) | (w << 4) | lo;

    float v[4];

    // ================= FWHT #1 =================
    {   // fused x*B load
        float4 xv = ((const float4*)(x + (size_t)row * DD))[k];
        float4 bv = ((const float4*)(B + sb))[k];
        v[0] = xv.x * bv.x; v[1] = xv.y * bv.y;
        v[2] = xv.z * bv.z; v[3] = xv.w * bv.w;
    }
    fwht_low7(v, l);                      // stages b0..b6

    #pragma unroll
    for (int r = 0; r < 4; r++) hs[sw(e1b + r)] = v[r];
    __syncthreads();
    #pragma unroll
    for (int j = 0; j < 4; j++) v[j] = hs[sw(e2b + (j << 8))];
    r4(v);                                // stages b8,b9
    shstage(v, l, 16);                    // stage b7 (l4)

    // write FWHT1 result at natural indices for the permutation gather.
    // Each thread writes exactly the locations it read above -> no sync needed.
    #pragma unroll
    for (int j = 0; j < 4; j++) hs[sw(e2b + (j << 8))] = v[j];
    __syncthreads();

    // ============ permutation gather * G (into phase-1 layout) ============
    {
        int4   pv = ((const int4*)(P + sb))[k];
        float4 gv = ((const float4*)(G + sb))[k];
        v[0] = hs[sw(pv.x - sb)] * gv.x;
        v[1] = hs[sw(pv.y - sb)] * gv.y;
        v[2] = hs[sw(pv.z - sb)] * gv.z;
        v[3] = hs[sw(pv.w - sb)] * gv.w;
    }

    // ================= FWHT #2 =================
    fwht_low7(v, l);                      // stages b0..b6
    __syncthreads();                      // all gathers done before overwrite
    #pragma unroll
    for (int r = 0; r < 4; r++) hs[sw(e1b + r)] = v[r];
    __syncthreads();
    #pragma unroll
    for (int j = 0; j < 4; j++) v[j] = hs[sw(e2b + (j << 8))];
    r4(v);                                // stages b8,b9
    shstage(v, l, 16);                    // stage b7

    // ================= epilogue =================
    const float c32 = 0.03125f;           // 1/(sigma*sqrt(D)) == sqrt(1/D) == 1/32
    float* orow = out + (size_t)row * (2 * SSTACK * DD) + sb;
    #pragma unroll
    for (int j = 0; j < 4; j++) {
        const int e = e2b + (j << 8);
        float t = c32 * v[j] * __ldg(S + sb + e);
        float sn, cs;
        sincosf(t, &sn, &cs);
        orow[e]               = c32 * cs + __ldg(bias + sb + e);
        orow[SSTACK * DD + e] = c32 * sn + __ldg(bias + SSTACK * DD + sb + e);
    }
}

extern "C" void kernel_launch(void* const* d_in, const int* in_sizes, int n_in,
                              void* d_out, int out_size) {
    // metadata order: x, B, G, S, bias, H (unused: FWHT replaces it), P
    const float* x    = (const float*)d_in[0];
    const float* B    = (const float*)d_in[1];
    const float* G    = (const float*)d_in[2];
    const float* S    = (const float*)d_in[3];
    const float* bias = (const float*)d_in[4];
    const int*   P    = (const int*)d_in[6];
    float* out = (float*)d_out;

    const int nrows = in_sizes[0] / DD;          // 8192
    dim3 grid(nrows * SSTACK);                   // one block per (row, stack)
    fastfood_kernel<<<grid, 256>>>(x, B, G, S, bias, P, out);
}

// round 8
// speedup vs baseline: 1.3822x; 1.0833x over previous
#include <cuda_runtime.h>

// FastFood layer: out[n, :] = 1/32 * [cos(t), sin(t)] + bias,
//   t = (1/32) * S .* FWHT( G .* Perm( FWHT( B .* x ) ) )   per stack.
// D = 1024, STACK = 4, out row = 8192 floats.
//
// One block = one (row, stack), 256 threads, 4 elements/thread.
// FWHT_1024: 2 bits radix-4 in registers, 5 bits via __shfl_xor,
// 3 cross-warp bits via ONE smem exchange (radix-4 regs + shfl mask 16).
// Swizzle sw(e) = e ^ (bit7<<4): conflict-free for all structured patterns
// AND float4-preserving -> STS.128 exchange writes, LDS.128 final read,
// fully vectorized epilogue with __sincosf.

#define DD 1024
#define SSTACK 4

__device__ __forceinline__ int sw(int e) {
    return e ^ (((e >> 7) & 1) << 4);
}

// radix-4 butterfly over v[0..3] holding {e, e+st, e+2st, e+3st}
__device__ __forceinline__ void r4(float v[4]) {
    float u0 = v[0] + v[1], u1 = v[0] - v[1];
    float u2 = v[2] + v[3], u3 = v[2] - v[3];
    v[0] = u0 + u2; v[1] = u1 + u3;
    v[2] = u0 - u2; v[3] = u1 - u3;
}

// one butterfly stage across lanes differing in bit mask m
__device__ __forceinline__ void shstage(float v[4], int l, int m) {
    #pragma unroll
    for (int r = 0; r < 4; r++) {
        float o = __shfl_xor_sync(0xffffffffu, v[r], m);
        v[r] = (l & m) ? (o - v[r]) : (v[r] + o);
    }
}

// 7 low stages: b0,b1 in registers; b2..b6 across lanes
__device__ __forceinline__ void fwht_low7(float v[4], int l) {
    r4(v);
    shstage(v, l, 1);
    shstage(v, l, 2);
    shstage(v, l, 4);
    shstage(v, l, 8);
    shstage(v, l, 16);
}

__global__ __launch_bounds__(256)
void fastfood_kernel(const float* __restrict__ x,
                     const float* __restrict__ B,
                     const float* __restrict__ G,
                     const float* __restrict__ S,
                     const float* __restrict__ bias,
                     const int*   __restrict__ P,
                     float* __restrict__ out)
{
    __shared__ float hs[DD];
    const int k  = threadIdx.x;      // 0..255
    const int w  = k >> 5;           // warp 0..7
    const int l  = k & 31;           // lane
    const int l4 = (l >> 4) & 1;
    const int lo = l & 15;
    const int row = blockIdx.x >> 2;
    const int s   = blockIdx.x & 3;
    const int sb  = s << 10;

    // phase-1: reg r holds element e1 = 4k + r  (float4 slot g, swizzled)
    // phase-2: reg j holds element e2 = j*256 + l4*128 + w*16 + lo
    const int g   = k ^ (((k >> 5) & 1) << 2);   // sw(4k)/4
    const int e2b = (l4 << 7) | (w << 4) | lo;

    float v[4];

    // ================= FWHT #1 =================
    {   // fused x*B load
        float4 xv = ((const float4*)(x + (size_t)row * DD))[k];
        float4 bv = ((const float4*)(B + sb))[k];
        v[0] = xv.x * bv.x; v[1] = xv.y * bv.y;
        v[2] = xv.z * bv.z; v[3] = xv.w * bv.w;
    }
    fwht_low7(v, l);                              // stages b0..b6

    ((float4*)hs)[g] = make_float4(v[0], v[1], v[2], v[3]);   // STS.128
    __syncthreads();
    #pragma unroll
    for (int j = 0; j < 4; j++) v[j] = hs[sw(e2b + (j << 8))];
    r4(v);                                        // stages b8,b9
    shstage(v, l, 16);                            // stage b7

    // write back to the thread's OWN slots (no sync needed before)
    #pragma unroll
    for (int j = 0; j < 4; j++) hs[sw(e2b + (j << 8))] = v[j];
    __syncthreads();

    // ============ permutation gather * G (into phase-1 layout) ============
    {
        int4   pv = ((const int4*)(P + sb))[k];
        float4 gv = ((const float4*)(G + sb))[k];
        v[0] = hs[sw(pv.x - sb)] * gv.x;
        v[1] = hs[sw(pv.y - sb)] * gv.y;
        v[2] = hs[sw(pv.z - sb)] * gv.z;
        v[3] = hs[sw(pv.w - sb)] * gv.w;
    }

    // ================= FWHT #2 =================
    fwht_low7(v, l);                              // stages b0..b6
    __syncthreads();                              // gathers done before overwrite
    ((float4*)hs)[g] = make_float4(v[0], v[1], v[2], v[3]);   // STS.128
    __syncthreads();
    #pragma unroll
    for (int j = 0; j < 4; j++) v[j] = hs[sw(e2b + (j << 8))];
    r4(v);                                        // stages b8,b9
    shstage(v, l, 16);                            // stage b7

    // final re-layout: write back to OWN slots, then contiguous float4 read
    #pragma unroll
    for (int j = 0; j < 4; j++) hs[sw(e2b + (j << 8))] = v[j];
    __syncthreads();

    // ================= vectorized epilogue =================
    {
        float4 h4  = ((const float4*)hs)[g];      // elements 4k..4k+3, LDS.128
        float4 s4  = ((const float4*)(S + sb))[k];
        float4 bc4 = ((const float4*)(bias + sb))[k];
        float4 bs4 = ((const float4*)(bias + SSTACK * DD + sb))[k];
        const float c32 = 0.03125f;               // 1/(sigma*sqrt(D)) == sqrt(1/D)

        float4 oc, os;
        float sn, cs;
        __sincosf(c32 * h4.x * s4.x, &sn, &cs);
        oc.x = c32 * cs + bc4.x;  os.x = c32 * sn + bs4.x;
        __sincosf(c32 * h4.y * s4.y, &sn, &cs);
        oc.y = c32 * cs + bc4.y;  os.y = c32 * sn + bs4.y;
        __sincosf(c32 * h4.z * s4.z, &sn, &cs);
        oc.z = c32 * cs + bc4.z;  os.z = c32 * sn + bs4.z;
        __sincosf(c32 * h4.w * s4.w, &sn, &cs);
        oc.w = c32 * cs + bc4.w;  os.w = c32 * sn + bs4.w;

        float* orow = out + (size_t)row * (2 * SSTACK * DD) + sb;
        ((float4*)orow)[k]                    = oc;   // cos half
        ((float4*)(orow + SSTACK * DD))[k]    = os;   // sin half
    }
}

extern "C" void kernel_launch(void* const* d_in, const int* in_sizes, int n_in,
                              void* d_out, int out_size) {
    // metadata order: x, B, G, S, bias, H (unused: FWHT replaces it), P
    const float* x    = (const float*)d_in[0];
    const float* B    = (const float*)d_in[1];
    const float* G    = (const float*)d_in[2];
    const float* S    = (const float*)d_in[3];
    const float* bias = (const float*)d_in[4];
    const int*   P    = (const int*)d_in[6];
    float* out = (float*)d_out;

    const int nrows = in_sizes[0] / DD;          // 8192
    dim3 grid(nrows * SSTACK);                   // one block per (row, stack)
    fastfood_kernel<<<grid, 256>>>(x, B, G, S, bias, P, out);
}

// round 10
// speedup vs baseline: 1.9700x; 1.4253x over previous
#include <cuda_runtime.h>

// FastFood layer: out[n, :] = 1/32 * [cos(t), sin(t)] + bias,
//   t = (1/32) * S .* FWHT( G .* Perm( FWHT( B .* x ) ) )   per stack.
// D = 1024, STACK = 4, out row = 8192 floats.
//
// ONE WARP per (row, stack): 32 threads x 32 elements in registers.
// FWHT_1024 = radix-32 in regs over bits {b0,b1,b7,b8,b9} (phase A, the
// bits encoded by float4 lane m and load index i), ONE warp-private smem
// exchange, radix-32 in regs over bits {b2..b6} (phase B). Zero shuffles,
// zero __syncthreads. Swizzle a(e)=e^(((e>>7)&7)<<2) keeps float4
// contiguity and is bank-conflict-free for every structured pattern here.
// Block = 8 warps = 8 independent units, 32KB smem.

#define DD 1024
#define SSTACK 4

__device__ __forceinline__ int swz(int e) {
    return e ^ (((e >> 7) & 7) << 2);
}

// full radix-32 butterfly network over the 5 register-index bits
__device__ __forceinline__ void fwht32(float v[32]) {
    #pragma unroll
    for (int st = 1; st < 32; st <<= 1) {
        #pragma unroll
        for (int r = 0; r < 32; r++) {
            if (!(r & st)) {
                float a = v[r], b = v[r | st];
                v[r]      = a + b;
                v[r | st] = a - b;
            }
        }
    }
}

__global__ __launch_bounds__(256)
void fastfood_kernel(const float* __restrict__ x,
                     const float* __restrict__ B,
                     const float* __restrict__ G,
                     const float* __restrict__ S,
                     const float* __restrict__ bias,
                     const int*   __restrict__ P,
                     float* __restrict__ out)
{
    __shared__ float buf[8][DD];
    const int l    = threadIdx.x & 31;          // lane
    const int wu   = threadIdx.x >> 5;          // warp (unit) in block
    const int unit = blockIdx.x * 8 + wu;       // global (row,stack)
    const int row  = unit >> 2;
    const int sb   = (unit & 3) << 10;
    float* hs = buf[wu];

    const int hi = l >> 2;                      // phase-B lane bits b9b8b7
    const int lo = l & 3;                       // phase-B lane bits b1b0

    // phase-A: reg r=(i<<2)|m holds element e = (i<<7) | (l<<2) | m
    // phase-B: reg c holds element e' = (hi<<7) | (c<<2) | lo
    float v[32];

    // ================= FWHT #1 =================
    const float* xr = x + (size_t)row * DD;
    #pragma unroll
    for (int i = 0; i < 8; i++) {               // fused x*B load, coalesced
        float4 xv = *(const float4*)(xr + (i << 7) + (l << 2));
        float4 bv = *(const float4*)(B + sb + (i << 7) + (l << 2));
        v[4*i+0] = xv.x * bv.x;  v[4*i+1] = xv.y * bv.y;
        v[4*i+2] = xv.z * bv.z;  v[4*i+3] = xv.w * bv.w;
    }
    fwht32(v);                                  // stages b0,b1,b7,b8,b9

    #pragma unroll
    for (int i = 0; i < 8; i++)                 // exchange write (STS.128)
        *(float4*)&hs[(i << 7) | ((l ^ i) << 2)] =
            make_float4(v[4*i], v[4*i+1], v[4*i+2], v[4*i+3]);
    __syncwarp();
    #pragma unroll
    for (int c = 0; c < 32; c++)                // exchange read (conflict-free)
        v[c] = hs[(hi << 7) | (((c ^ hi) & 31) << 2) | lo];
    fwht32(v);                                  // stages b2..b6  -> FWHT1 done

    #pragma unroll
    for (int c = 0; c < 32; c++)                // write back to OWN slots
        hs[(hi << 7) | (((c ^ hi) & 31) << 2) | lo] = v[c];
    __syncwarp();

    // ============ permutation gather * G (into phase-A ownership) ============
    #pragma unroll
    for (int i = 0; i < 8; i++) {
        int4   pv = *(const int4*)(P + sb + (i << 7) + (l << 2));
        float4 gv = *(const float4*)(G + sb + (i << 7) + (l << 2));
        v[4*i+0] = hs[swz(pv.x - sb)] * gv.x;
        v[4*i+1] = hs[swz(pv.y - sb)] * gv.y;
        v[4*i+2] = hs[swz(pv.z - sb)] * gv.z;
        v[4*i+3] = hs[swz(pv.w - sb)] * gv.w;
    }
    __syncwarp();                               // gathers done before overwrite

    // ================= FWHT #2 =================
    fwht32(v);                                  // stages b0,b1,b7,b8,b9
    #pragma unroll
    for (int i = 0; i < 8; i++)
        *(float4*)&hs[(i << 7) | ((l ^ i) << 2)] =
            make_float4(v[4*i], v[4*i+1], v[4*i+2], v[4*i+3]);
    __syncwarp();
    #pragma unroll
    for (int c = 0; c < 32; c++)
        v[c] = hs[(hi << 7) | (((c ^ hi) & 31) << 2) | lo];
    fwht32(v);                                  // stages b2..b6  -> FWHT2 done

    #pragma unroll
    for (int c = 0; c < 32; c++)                // write back to OWN slots
        hs[(hi << 7) | (((c ^ hi) & 31) << 2) | lo] = v[c];
    __syncwarp();

    // ================= vectorized epilogue =================
    const float c32 = 0.03125f;                 // 1/(sigma*sqrt(D)) == sqrt(1/D)
    float* orow = out + (size_t)row * (2 * SSTACK * DD) + sb;
    #pragma unroll
    for (int i = 0; i < 8; i++) {
        float4 h4  = *(const float4*)&hs[(i << 7) | ((l ^ i) << 2)];  // LDS.128
        float4 s4  = *(const float4*)(S + sb + (i << 7) + (l << 2));
        float4 bc4 = *(const float4*)(bias + sb + (i << 7) + (l << 2));
        float4 bs4 = *(const float4*)(bias + SSTACK * DD + sb + (i << 7) + (l << 2));

        float4 oc, os;
        float sn, cs;
        __sincosf(c32 * h4.x * s4.x, &sn, &cs);
        oc.x = c32 * cs + bc4.x;  os.x = c32 * sn + bs4.x;
        __sincosf(c32 * h4.y * s4.y, &sn, &cs);
        oc.y = c32 * cs + bc4.y;  os.y = c32 * sn + bs4.y;
        __sincosf(c32 * h4.z * s4.z, &sn, &cs);
        oc.z = c32 * cs + bc4.z;  os.z = c32 * sn + bs4.z;
        __sincosf(c32 * h4.w * s4.w, &sn, &cs);
        oc.w = c32 * cs + bc4.w;  os.w = c32 * sn + bs4.w;

        *(float4*)(orow + (i << 7) + (l << 2))                = oc;  // cos half
        *(float4*)(orow + SSTACK * DD + (i << 7) + (l << 2))  = os;  // sin half
    }
}

extern "C" void kernel_launch(void* const* d_in, const int* in_sizes, int n_in,
                              void* d_out, int out_size) {
    // metadata order: x, B, G, S, bias, H (unused: FWHT replaces it), P
    const float* x    = (const float*)d_in[0];
    const float* B    = (const float*)d_in[1];
    const float* G    = (const float*)d_in[2];
    const float* S    = (const float*)d_in[3];
    const float* bias = (const float*)d_in[4];
    const int*   P    = (const int*)d_in[6];
    float* out = (float*)d_out;

    const int nrows = in_sizes[0] / DD;              // 8192
    const int nunits = nrows * SSTACK;               // 32768 (row,stack) units
    dim3 grid(nunits / 8);                           // 8 warp-units per block
    fastfood_kernel<<<grid, 256>>>(x, B, G, S, bias, P, out);
}

// round 14
// speedup vs baseline: 1.9803x; 1.0052x over previous
#include <cuda_runtime.h>

// FastFood layer: out[n, :] = 1/32 * [cos(t), sin(t)] + bias,
//   t = (1/32) * S .* FWHT( G .* Perm( FWHT( B .* x ) ) )   per stack.
// D = 1024, STACK = 4, out row = 8192 floats.
//
// ONE WARP per (row, stack): 32 threads x 32 elements in registers.
// FWHT_1024 = radix-32 in regs over bits {b0,b1,b7,b8,b9}, ONE warp-private
// smem exchange, radix-32 in regs over bits {b2..b6}. Zero shuffles, zero
// __syncthreads. Swizzle a(e)=e^(((e>>7)&7)<<2) keeps float4 contiguity and
// is conflict-free for all structured patterns.
//
// Param traffic compressed by a tiny prep pass (graph-capturable, runs every
// call, __device__ scratch only):
//   Bb  : B as sign bytes (0x00/0x80), applied to x via PRMT+XOR  (4x less wf)
//   P16 : (P - stack_base) as int16 with the smem swizzle pre-applied (2x)
//   Ssc : S * (1/32) pre-scaled
//   bias_nz : 0 if bias is identically zero -> epilogue skips bias loads
//             (falls back to loading bias when nonzero).

#define DD 1024
#define SSTACK 4
#define NE (SSTACK * DD)        // 4096

__device__ __align__(16) short         g_P16[NE];
__device__ __align__(16) float         g_Ssc[NE];
__device__ __align__(16) unsigned char g_Bb[NE];
__device__ int g_bias_nz;

__device__ __forceinline__ int swz(int e) {
    return e ^ (((e >> 7) & 7) << 2);
}

// full radix-32 butterfly network over the 5 register-index bits
__device__ __forceinline__ void fwht32(float v[32]) {
    #pragma unroll
    for (int st = 1; st < 32; st <<= 1) {
        #pragma unroll
        for (int r = 0; r < 32; r++) {
            if (!(r & st)) {
                float a = v[r], b = v[r | st];
                v[r]      = a + b;
                v[r | st] = a - b;
            }
        }
    }
}

__global__ __launch_bounds__(256)
void prep_kernel(const int*   __restrict__ P,
                 const float* __restrict__ S,
                 const float* __restrict__ B,
                 const float* __restrict__ bias)
{
    if (blockIdx.x < 16) {
        const int e  = blockIdx.x * 256 + threadIdx.x;     // 0..4095
        const int sb = (e >> 10) << 10;
        g_P16[e] = (short)swz(P[e] - sb);
        g_Ssc[e] = S[e] * 0.03125f;
        g_Bb[e]  = (B[e] < 0.0f) ? 0x80u : 0x00u;
    } else {
        int nz = 0;
        for (int i = threadIdx.x; i < 2 * NE; i += 256)
            nz |= (bias[i] != 0.0f);
        nz = __syncthreads_or(nz);
        if (threadIdx.x == 0) g_bias_nz = nz;
    }
}

__global__ __launch_bounds__(256)
void fastfood_kernel(const float* __restrict__ x,
                     const float* __restrict__ G,
                     const float* __restrict__ bias,
                     float* __restrict__ out)
{
    __shared__ float buf[8][DD];
    const int l    = threadIdx.x & 31;          // lane
    const int wu   = threadIdx.x >> 5;          // warp (unit) in block
    const int unit = blockIdx.x * 8 + wu;       // global (row,stack)
    const int row  = unit >> 2;
    const int sb   = (unit & 3) << 10;
    float* hs = buf[wu];

    const int hi = l >> 2;                      // phase-B lane bits b9b8b7
    const int lo = l & 3;                       // phase-B lane bits b1b0

    // phase-A: reg r=(i<<2)|m holds element e = (i<<7) | (l<<2) | m
    // phase-B: reg c holds element e' = (hi<<7) | (c<<2) | lo
    float v[32];

    // ================= FWHT #1 =================
    const float* xr = x + (size_t)row * DD;
    #pragma unroll
    for (int i = 0; i < 8; i++) {               // fused x*B, B = sign bytes
        float4   xv = *(const float4*)(xr + (i << 7) + (l << 2));
        unsigned bw = *(const unsigned*)(g_Bb + sb + (i << 7) + (l << 2));
        v[4*i+0] = __int_as_float(__float_as_int(xv.x) ^ (int)__byte_perm(bw, 0, 0x0444));
        v[4*i+1] = __int_as_float(__float_as_int(xv.y) ^ (int)__byte_perm(bw, 0, 0x1444));
        v[4*i+2] = __int_as_float(__float_as_int(xv.z) ^ (int)__byte_perm(bw, 0, 0x2444));
        v[4*i+3] = __int_as_float(__float_as_int(xv.w) ^ (int)__byte_perm(bw, 0, 0x3444));
    }
    fwht32(v);                                  // stages b0,b1,b7,b8,b9

    #pragma unroll
    for (int i = 0; i < 8; i++)                 // exchange write (STS.128)
        *(float4*)&hs[(i << 7) | ((l ^ i) << 2)] =
            make_float4(v[4*i], v[4*i+1], v[4*i+2], v[4*i+3]);
    __syncwarp();
    #pragma unroll
    for (int c = 0; c < 32; c++)                // exchange read (conflict-free)
        v[c] = hs[(hi << 7) | (((c ^ hi) & 31) << 2) | lo];
    fwht32(v);                                  // stages b2..b6  -> FWHT1 done

    #pragma unroll
    for (int c = 0; c < 32; c++)                // write back to OWN slots
        hs[(hi << 7) | (((c ^ hi) & 31) << 2) | lo] = v[c];
    __syncwarp();

    // ====== permutation gather * G (pre-swizzled int16 indices) ======
    #pragma unroll
    for (int i = 0; i < 8; i++) {
        short4 pv = *(const short4*)(g_P16 + sb + (i << 7) + (l << 2));
        float4 gv = *(const float4*)(G + sb + (i << 7) + (l << 2));
        v[4*i+0] = hs[pv.x] * gv.x;
        v[4*i+1] = hs[pv.y] * gv.y;
        v[4*i+2] = hs[pv.z] * gv.z;
        v[4*i+3] = hs[pv.w] * gv.w;
    }
    __syncwarp();                               // gathers done before overwrite

    // ================= FWHT #2 =================
    fwht32(v);                                  // stages b0,b1,b7,b8,b9
    #pragma unroll
    for (int i = 0; i < 8; i++)
        *(float4*)&hs[(i << 7) | ((l ^ i) << 2)] =
            make_float4(v[4*i], v[4*i+1], v[4*i+2], v[4*i+3]);
    __syncwarp();
    #pragma unroll
    for (int c = 0; c < 32; c++)
        v[c] = hs[(hi << 7) | (((c ^ hi) & 31) << 2) | lo];
    fwht32(v);                                  // stages b2..b6  -> FWHT2 done

    #pragma unroll
    for (int c = 0; c < 32; c++)                // write back to OWN slots
        hs[(hi << 7) | (((c ^ hi) & 31) << 2) | lo] = v[c];
    __syncwarp();

    // ================= vectorized epilogue =================
    const float c32 = 0.03125f;                 // sqrt(1/D)
    float* orow = out + (size_t)row * (2 * NE) + sb;
    const int bnz = g_bias_nz;                  // uniform

    if (!bnz) {
        #pragma unroll
        for (int i = 0; i < 8; i++) {
            float4 h4 = *(const float4*)&hs[(i << 7) | ((l ^ i) << 2)];
            float4 s4 = *(const float4*)(g_Ssc + sb + (i << 7) + (l << 2));
            float4 oc, os; float sn, cs;
            __sincosf(h4.x * s4.x, &sn, &cs); oc.x = c32 * cs; os.x = c32 * sn;
            __sincosf(h4.y * s4.y, &sn, &cs); oc.y = c32 * cs; os.y = c32 * sn;
            __sincosf(h4.z * s4.z, &sn, &cs); oc.z = c32 * cs; os.z = c32 * sn;
            __sincosf(h4.w * s4.w, &sn, &cs); oc.w = c32 * cs; os.w = c32 * sn;
            *(float4*)(orow + (i << 7) + (l << 2))      = oc;   // cos half
            *(float4*)(orow + NE + (i << 7) + (l << 2)) = os;   // sin half
        }
    } else {
        #pragma unroll
        for (int i = 0; i < 8; i++) {
            float4 h4  = *(const float4*)&hs[(i << 7) | ((l ^ i) << 2)];
            float4 s4  = *(const float4*)(g_Ssc + sb + (i << 7) + (l << 2));
            float4 bc4 = *(const float4*)(bias + sb + (i << 7) + (l << 2));
            float4 bs4 = *(const float4*)(bias + NE + sb + (i << 7) + (l << 2));
            float4 oc, os; float sn, cs;
            __sincosf(h4.x * s4.x, &sn, &cs); oc.x = c32*cs + bc4.x; os.x = c32*sn + bs4.x;
            __sincosf(h4.y * s4.y, &sn, &cs); oc.y = c32*cs + bc4.y; os.y = c32*sn + bs4.y;
            __sincosf(h4.z * s4.z, &sn, &cs); oc.z = c32*cs + bc4.z; os.z = c32*sn + bs4.z;
            __sincosf(h4.w * s4.w, &sn, &cs); oc.w = c32*cs + bc4.w; os.w = c32*sn + bs4.w;
            *(float4*)(orow + (i << 7) + (l << 2))      = oc;
            *(float4*)(orow + NE + (i << 7) + (l << 2)) = os;
        }
    }
}

extern "C" void kernel_launch(void* const* d_in, const int* in_sizes, int n_in,
                              void* d_out, int out_size) {
    // metadata order: x, B, G, S, bias, H (unused: FWHT replaces it), P
    const float* x    = (const float*)d_in[0];
    const float* B    = (const float*)d_in[1];
    const float* G    = (const float*)d_in[2];
    const float* S    = (const float*)d_in[3];
    const float* bias = (const float*)d_in[4];
    const int*   P    = (const int*)d_in[6];
    float* out = (float*)d_out;

    prep_kernel<<<17, 256>>>(P, S, B, bias);

    const int nrows = in_sizes[0] / DD;              // 8192
    const int nunits = nrows * SSTACK;               // 32768 (row,stack) units
    fastfood_kernel<<<nunits / 8, 256>>>(x, G, bias, out);
}

// round 16
// speedup vs baseline: 2.3613x; 1.1924x over previous
#include <cuda_runtime.h>

// FastFood layer: out[n, :] = 1/32 * [cos(t), sin(t)] + bias,
//   t = (1/32) * S .* FWHT( G .* Perm( FWHT( B .* x ) ) )   per stack.
// D = 1024, STACK = 4, out row = 8192 floats.
//
// ONE WARP per (row, stack): 32 threads x 32 elements in registers.
// FWHT_1024 factored over bits {b0,b1,b7,b8,b9} (register butterfly, phase A)
// and {b2..b6} (register butterfly, phase B) with ONE smem exchange between.
// Stages commute, so FWHT1 runs A->B (ending fully in smem for the random
// permutation gather) and FWHT2 runs B->A (gather straight into phase-B regs,
// end in phase-A regs -> epilogue needs NO smem reads).
// Swizzled storage addr(e) = e ^ (((e>>7)&7)<<2): float4-preserving and
// conflict-free for every structured access here.
//
// Prep pass (16 blocks, graph-capturable, __device__ scratch only):
//   Bb   : B as sign bytes, applied to x via PRMT+XOR
//   P16p : gather indices as int16, smem-swizzle pre-applied, re-packed into
//          the phase-B [c][lane] order so gather param loads stay coalesced
//   Gp   : G re-packed into the same [c][lane] order
//   Ssc  : S * (1/32)
//   g_bnz[16] : per-block bias-nonzero flags (bias add skipped when all zero)

#define DD 1024
#define SSTACK 4
#define NE (SSTACK * DD)        // 4096

__device__ __align__(16) short g_P16p[NE];
__device__ __align__(16) float g_Gp[NE];
__device__ __align__(16) float g_Ssc[NE];
__device__ __align__(16) unsigned char g_Bb[NE];
__device__ __align__(16) int g_bnz[16];

__device__ __forceinline__ int swz(int e) {
    return e ^ (((e >> 7) & 7) << 2);
}

// full radix-32 butterfly network over the 5 register-index bits
__device__ __forceinline__ void fwht32(float v[32]) {
    #pragma unroll
    for (int st = 1; st < 32; st <<= 1) {
        #pragma unroll
        for (int r = 0; r < 32; r++) {
            if (!(r & st)) {
                float a = v[r], b = v[r | st];
                v[r]      = a + b;
                v[r | st] = a - b;
            }
        }
    }
}

__global__ __launch_bounds__(256)
void prep_kernel(const int*   __restrict__ P,
                 const float* __restrict__ S,
                 const float* __restrict__ B,
                 const float* __restrict__ G,
                 const float* __restrict__ bias)
{
    const int t = blockIdx.x * 256 + threadIdx.x;      // 0..4095
    // natural-order params
    g_Ssc[t] = S[t] * 0.03125f;
    g_Bb[t]  = (B[t] < 0.0f) ? 0x80u : 0x00u;

    // phase-B-packed gather params: t = sb + (cp<<6)|(l<<1)|par
    {
        const int sb  = (t >> 10) << 10;
        const int j   = t & 1023;
        const int cp  = j >> 6;
        const int l   = (j >> 1) & 31;
        const int par = j & 1;
        const int c   = (cp << 1) | par;
        const int ep  = ((l >> 2) << 7) | (c << 2) | (l & 3);   // phase-B element
        g_P16p[t] = (short)swz(P[sb + ep] - sb);
        g_Gp[t]   = G[sb + ep];
    }

    // distributed bias scan: block b checks bias[b*512 .. b*512+512)
    int nz = 0;
    const int base = blockIdx.x * 512 + threadIdx.x;
    nz |= (bias[base] != 0.0f);
    nz |= (bias[base + 256] != 0.0f);
    nz = __syncthreads_or(nz);
    if (threadIdx.x == 0) g_bnz[blockIdx.x] = nz;
}

__global__ __launch_bounds__(256, 3)
void fastfood_kernel(const float* __restrict__ x,
                     const float* __restrict__ bias,
                     float* __restrict__ out)
{
    __shared__ float buf[8][DD];
    const int l    = threadIdx.x & 31;          // lane
    const int wu   = threadIdx.x >> 5;          // warp (unit) in block
    const int unit = blockIdx.x * 8 + wu;       // global (row,stack)
    const int row  = unit >> 2;
    const int sb   = (unit & 3) << 10;
    float* hs = buf[wu];

    const int hi = l >> 2;                      // phase-B lane bits b9b8b7
    const int lo = l & 3;                       // phase-B lane bits b1b0

    // bias-nonzero flag (uniform; 4 broadcast loads)
    int bnz;
    {
        int4 f0 = *(const int4*)(g_bnz);
        int4 f1 = *(const int4*)(g_bnz + 4);
        int4 f2 = *(const int4*)(g_bnz + 8);
        int4 f3 = *(const int4*)(g_bnz + 12);
        bnz = f0.x | f0.y | f0.z | f0.w | f1.x | f1.y | f1.z | f1.w |
              f2.x | f2.y | f2.z | f2.w | f3.x | f3.y | f3.z | f3.w;
    }

    // phase-A: reg r=(i<<2)|m holds element e  = (i<<7) | (l<<2) | m
    // phase-B: reg c        holds element e' = (hi<<7) | (c<<2) | lo
    float v[32];

    // ================= FWHT #1  (A -> B, ends in smem) =================
    const float* xr = x + (size_t)row * DD;
    #pragma unroll
    for (int i = 0; i < 8; i++) {               // fused x*B, B = sign bytes
        float4   xv = *(const float4*)(xr + (i << 7) + (l << 2));
        unsigned bw = *(const unsigned*)(g_Bb + sb + (i << 7) + (l << 2));
        v[4*i+0] = __int_as_float(__float_as_int(xv.x) ^ (int)__byte_perm(bw, 0, 0x0444));
        v[4*i+1] = __int_as_float(__float_as_int(xv.y) ^ (int)__byte_perm(bw, 0, 0x1444));
        v[4*i+2] = __int_as_float(__float_as_int(xv.z) ^ (int)__byte_perm(bw, 0, 0x2444));
        v[4*i+3] = __int_as_float(__float_as_int(xv.w) ^ (int)__byte_perm(bw, 0, 0x3444));
    }
    fwht32(v);                                  // stages b0,b1,b7,b8,b9

    #pragma unroll
    for (int i = 0; i < 8; i++)                 // exchange write (STS.128)
        *(float4*)&hs[(i << 7) | ((l ^ i) << 2)] =
            make_float4(v[4*i], v[4*i+1], v[4*i+2], v[4*i+3]);
    __syncwarp();
    #pragma unroll
    for (int c = 0; c < 32; c++)                // exchange read (conflict-free)
        v[c] = hs[(hi << 7) | (((c ^ hi) & 31) << 2) | lo];
    fwht32(v);                                  // stages b2..b6  -> FWHT1 done

    #pragma unroll
    for (int c = 0; c < 32; c++)                // full result into smem (own slots)
        hs[(hi << 7) | (((c ^ hi) & 31) << 2) | lo] = v[c];
    __syncwarp();

    // ====== permutation gather * G straight into phase-B registers ======
    #pragma unroll
    for (int cp = 0; cp < 16; cp++) {
        short2 pv = *(const short2*)(g_P16p + sb + (cp << 6) + (l << 1));
        float2 gv = *(const float2*)(g_Gp   + sb + (cp << 6) + (l << 1));
        v[2*cp + 0] = hs[pv.x] * gv.x;
        v[2*cp + 1] = hs[pv.y] * gv.y;
    }
    __syncwarp();                               // gathers done before overwrite

    // ================= FWHT #2  (B -> A, ends in registers) =================
    fwht32(v);                                  // stages b2..b6
    #pragma unroll
    for (int c = 0; c < 32; c++)                // exchange write (conflict-free)
        hs[(hi << 7) | (((c ^ hi) & 31) << 2) | lo] = v[c];
    __syncwarp();
    #pragma unroll
    for (int i = 0; i < 8; i++) {               // exchange read (LDS.128)
        float4 h4 = *(const float4*)&hs[(i << 7) | ((l ^ i) << 2)];
        v[4*i+0] = h4.x; v[4*i+1] = h4.y; v[4*i+2] = h4.z; v[4*i+3] = h4.w;
    }
    fwht32(v);                                  // stages b0,b1,b7,b8,b9 -> done

    // ================= epilogue (registers only) =================
    const float c32 = 0.03125f;                 // sqrt(1/D)
    float* orow = out + (size_t)row * (2 * NE) + sb;
    if (!bnz) {
        #pragma unroll
        for (int i = 0; i < 8; i++) {
            float4 s4 = *(const float4*)(g_Ssc + sb + (i << 7) + (l << 2));
            float4 oc, os; float sn, cs;
            __sincosf(v[4*i+0] * s4.x, &sn, &cs); oc.x = c32 * cs; os.x = c32 * sn;
            __sincosf(v[4*i+1] * s4.y, &sn, &cs); oc.y = c32 * cs; os.y = c32 * sn;
            __sincosf(v[4*i+2] * s4.z, &sn, &cs); oc.z = c32 * cs; os.z = c32 * sn;
            __sincosf(v[4*i+3] * s4.w, &sn, &cs); oc.w = c32 * cs; os.w = c32 * sn;
            *(float4*)(orow + (i << 7) + (l << 2))      = oc;   // cos half
            *(float4*)(orow + NE + (i << 7) + (l << 2)) = os;   // sin half
        }
    } else {
        #pragma unroll
        for (int i = 0; i < 8; i++) {
            float4 s4  = *(const float4*)(g_Ssc + sb + (i << 7) + (l << 2));
            float4 bc4 = *(const float4*)(bias + sb + (i << 7) + (l << 2));
            float4 bs4 = *(const float4*)(bias + NE + sb + (i << 7) + (l << 2));
            float4 oc, os; float sn, cs;
            __sincosf(v[4*i+0] * s4.x, &sn, &cs); oc.x = c32*cs + bc4.x; os.x = c32*sn + bs4.x;
            __sincosf(v[4*i+1] * s4.y, &sn, &cs); oc.y = c32*cs + bc4.y; os.y = c32*sn + bs4.y;
            __sincosf(v[4*i+2] * s4.z, &sn, &cs); oc.z = c32*cs + bc4.z; os.z = c32*sn + bs4.z;
            __sincosf(v[4*i+3] * s4.w, &sn, &cs); oc.w = c32*cs + bc4.w; os.w = c32*sn + bs4.w;
            *(float4*)(orow + (i << 7) + (l << 2))      = oc;
            *(float4*)(orow + NE + (i << 7) + (l << 2)) = os;
        }
    }
}

extern "C" void kernel_launch(void* const* d_in, const int* in_sizes, int n_in,
                              void* d_out, int out_size) {
    // metadata order: x, B, G, S, bias, H (unused: FWHT replaces it), P
    const float* x    = (const float*)d_in[0];
    const float* B    = (const float*)d_in[1];
    const float* G    = (const float*)d_in[2];
    const float* S    = (const float*)d_in[3];
    const float* bias = (const float*)d_in[4];
    const int*   P    = (const int*)d_in[6];
    float* out = (float*)d_out;

    prep_kernel<<<16, 256>>>(P, S, B, G, bias);

    const int nrows = in_sizes[0] / DD;              // 8192
    const int nunits = nrows * SSTACK;               // 32768 (row,stack) units
    fastfood_kernel<<<nunits / 8, 256>>>(x, bias, out);
}